// round 12
// baseline (speedup 1.0000x reference)
#include <cuda_runtime.h>
#include <cstdint>

// PScan: Y_t = A_t @ Y_{t-1} + X_t  (Y_0 = X_0), per (b,c) chain.
// Shapes: A,X,Y = [B=4, L=2048, C=16, 16, 16] fp32, row-major.
// Chunked scan (TT=32), cp.async staging, f32x2 FFMA, split-k half-warps.
// Phase3: TWO chunks per warp (interleaved ILP) + direct streaming STG.32.

#define BB 4
#define LL 2048
#define CC 16
#define TT 32
#define NCHUNK (LL / TT)            // 64
#define CHAINS (BB * CC)            // 64
#define TOTCHUNK (CHAINS * NCHUNK)  // 4096
#define STEP_STRIDE (CC * 256)

typedef unsigned long long u64;

__device__ float g_Pagg[TOTCHUNK * 256];
__device__ float g_Zagg[TOTCHUNK * 256];
__device__ float g_carry[TOTCHUNK * 256];

__device__ __forceinline__ u64 ffma2(u64 a, u64 b, u64 c) {
    u64 d;
    asm("fma.rn.f32x2 %0, %1, %2, %3;" : "=l"(d) : "l"(a), "l"(b), "l"(c));
    return d;
}
__device__ __forceinline__ u64 add2(u64 a, u64 b) {
    u64 d;
    asm("add.rn.f32x2 %0, %1, %2;" : "=l"(d) : "l"(a), "l"(b));
    return d;
}
__device__ __forceinline__ u64 pack2(float lo, float hi) {
    u64 d;
    asm("mov.b64 %0, {%1, %2};" : "=l"(d) : "f"(lo), "f"(hi));
    return d;
}
__device__ __forceinline__ void unpack2(u64 v, float& lo, float& hi) {
    asm("mov.b64 {%0, %1}, %2;" : "=f"(lo), "=f"(hi) : "l"(v));
}

__device__ __forceinline__ void cp16(float* smem_dst, const float* gsrc) {
    uint32_t s = (uint32_t)__cvta_generic_to_shared(smem_dst);
    asm volatile("cp.async.ca.shared.global [%0], [%1], 16;\n" :: "r"(s), "l"(gsrc));
}
#define CP_COMMIT() asm volatile("cp.async.commit_group;\n" ::: "memory")
#define CP_WAIT0()  asm volatile("cp.async.wait_group 0;\n" ::: "memory")
#define CP_WAIT1()  asm volatile("cp.async.wait_group 1;\n" ::: "memory")
#define CP_WAIT2()  asm volatile("cp.async.wait_group 2;\n" ::: "memory")
#define CP_WAIT7()  asm volatile("cp.async.wait_group 7;\n" ::: "memory")

// partial dot of one A-row k-half (a0,a1 = 4 f32x2) with packed state st[4]
__device__ __forceinline__ float dot8(ulonglong2 a0, ulonglong2 a1, const u64* st)
{
    u64 acc0 = ffma2(a0.x, st[0], 0ull);
    u64 acc1 = ffma2(a0.y, st[1], 0ull);
    acc0 = ffma2(a1.x, st[2], acc0);
    acc1 = ffma2(a1.y, st[3], acc1);
    float lo, hi;
    unpack2(add2(acc0, acc1), lo, hi);
    return lo + hi;
}

// one split-k recurrence step for one chunk stream (Z only, with X add)
__device__ __forceinline__ void step_z(const float* As, int h, int j,
                                       u64* zst)
{
    const float* Xs = As + 256;
    const float* Ah = As + h * 8;

    float zpL[8], zpH[8];
#pragma unroll
    for (int r = 0; r < 8; r++) {
        ulonglong2 a0 = *(const ulonglong2*)(Ah + r * 16);
        ulonglong2 a1 = *(const ulonglong2*)(Ah + r * 16 + 4);
        zpL[r] = dot8(a0, a1, zst);
        ulonglong2 b0 = *(const ulonglong2*)(Ah + (8 + r) * 16);
        ulonglong2 b1 = *(const ulonglong2*)(Ah + (8 + r) * 16 + 4);
        zpH[r] = dot8(b0, b1, zst);
    }

    float zn[8];
#pragma unroll
    for (int r = 0; r < 8; r++) {
        float zsend = h ? zpL[r] : zpH[r];
        float zrecv = __shfl_xor_sync(0xffffffffu, zsend, 16);
        float zown  = h ? zpH[r] : zpL[r];
        float xv = Xs[(8 * h + r) * 16 + j];
        zn[r] = zown + zrecv + xv;
    }
#pragma unroll
    for (int mm = 0; mm < 4; mm++)
        zst[mm] = pack2(zn[2 * mm], zn[2 * mm + 1]);
}

// ============================================================================
// Phase 1 (R4/R7-proven): chunk aggregates, depth-2 double buffer, split-k.
// ============================================================================
__global__ void __launch_bounds__(64) phase1_kernel(
    const float* __restrict__ A, const float* __restrict__ X)
{
    __shared__ __align__(16) float sm[2][2][512];  // [warp][buf][A:256|X:256]

    const int wid  = threadIdx.x >> 5;
    const int lane = threadIdx.x & 31;
    const int w    = blockIdx.x * 2 + wid;
    const int chain = w / NCHUNK;
    const int chunk = w % NCHUNK;
    const int b = chain >> 4;
    const int c = chain & 15;
    const int t0 = chunk * TT;
    const int j = lane & 15;
    const int h = lane >> 4;

    const int base0 = ((b * LL + t0) * CC + c) * 256;
    const float* src = (h == 0 ? A : X) + base0 + j * 4;
    float* dst0 = sm[wid][0] + (h == 0 ? 0 : 256) + j * 4;
    float* dst1 = sm[wid][1] + (h == 0 ? 0 : 256) + j * 4;

#pragma unroll
    for (int q = 0; q < 4; q++) cp16(dst0 + q * 64, src + q * 64);
    CP_COMMIT();

    u64 zst[4], pst[4];
#pragma unroll
    for (int mm = 0; mm < 4; mm++) {
        zst[mm] = 0ull;
        int k0 = 8 * h + 2 * mm;
        pst[mm] = pack2(j == k0 ? 1.f : 0.f, j == k0 + 1 ? 1.f : 0.f);
    }

#pragma unroll 1
    for (int t = 0; t < TT; t++) {
        if (t + 1 < TT) {
            const float* s2 = src + (t + 1) * STEP_STRIDE;
            float* dn = (t & 1) ? dst0 : dst1;
#pragma unroll
            for (int q = 0; q < 4; q++) cp16(dn + q * 64, s2 + q * 64);
            CP_COMMIT();
            CP_WAIT1();
        } else {
            CP_WAIT0();
        }
        __syncwarp();

        const float* As = sm[wid][t & 1];
        const float* Xs = As + 256;
        const float* Ah = As + h * 8;

        float zpL[8], zpH[8], ppL[8], ppH[8];
#pragma unroll
        for (int r = 0; r < 8; r++) {
            ulonglong2 a0 = *(const ulonglong2*)(Ah + r * 16);
            ulonglong2 a1 = *(const ulonglong2*)(Ah + r * 16 + 4);
            zpL[r] = dot8(a0, a1, zst);
            ppL[r] = dot8(a0, a1, pst);
            ulonglong2 b0 = *(const ulonglong2*)(Ah + (8 + r) * 16);
            ulonglong2 b1 = *(const ulonglong2*)(Ah + (8 + r) * 16 + 4);
            zpH[r] = dot8(b0, b1, zst);
            ppH[r] = dot8(b0, b1, pst);
        }

        float zn[8], pn[8];
#pragma unroll
        for (int r = 0; r < 8; r++) {
            float zsend = h ? zpL[r] : zpH[r];
            float zrecv = __shfl_xor_sync(0xffffffffu, zsend, 16);
            float zown  = h ? zpH[r] : zpL[r];
            float xv = Xs[(8 * h + r) * 16 + j];
            zn[r] = zown + zrecv + xv;

            float psend = h ? ppL[r] : ppH[r];
            float precv = __shfl_xor_sync(0xffffffffu, psend, 16);
            float pown  = h ? ppH[r] : ppL[r];
            pn[r] = pown + precv;
        }
#pragma unroll
        for (int mm = 0; mm < 4; mm++) {
            zst[mm] = pack2(zn[2 * mm], zn[2 * mm + 1]);
            pst[mm] = pack2(pn[2 * mm], pn[2 * mm + 1]);
        }
        __syncwarp();
    }

    const int ab = w * 256;
#pragma unroll
    for (int mm = 0; mm < 4; mm++) {
        const int row = 8 * h + 2 * mm;
        float lo, hi;
        unpack2(zst[mm], lo, hi);
        g_Zagg[ab + row * 16 + j] = lo;
        g_Zagg[ab + (row + 1) * 16 + j] = hi;
        unpack2(pst[mm], lo, hi);
        g_Pagg[ab + row * 16 + j] = lo;
        g_Pagg[ab + (row + 1) * 16 + j] = hi;
    }
}

// ============================================================================
// Phase 2: per-chain scan of NCHUNK aggregates, depth-8 cp.async pipeline.
// ============================================================================
#define P2D 8

__global__ void phase2_kernel()
{
    __shared__ __align__(16) float sP[P2D][256];
    __shared__ __align__(16) float sZ[P2D][256];

    const int chain = blockIdx.x;
    const int lane  = threadIdx.x;
    const int col   = lane & 15;
    const bool zside = (lane < 16);

    const float* Pbase = g_Pagg + (size_t)chain * NCHUNK * 256;
    const float* Zbase = g_Zagg + (size_t)chain * NCHUNK * 256;

#pragma unroll 1
    for (int d = 0; d < P2D - 1; d++) {
        cp16(sP[d] + lane * 8,     Pbase + d * 256 + lane * 8);
        cp16(sP[d] + lane * 8 + 4, Pbase + d * 256 + lane * 8 + 4);
        cp16(sZ[d] + lane * 8,     Zbase + d * 256 + lane * 8);
        cp16(sZ[d] + lane * 8 + 4, Zbase + d * 256 + lane * 8 + 4);
        CP_COMMIT();
    }

    u64 ypk[8];
#pragma unroll
    for (int m = 0; m < 8; m++) ypk[m] = 0ull;

#pragma unroll 1
    for (int cix = 0; cix < NCHUNK; cix++) {
        const int buf = cix & (P2D - 1);
        const int pre = cix + P2D - 1;
        if (pre < NCHUNK) {
            const int pb = pre & (P2D - 1);
            cp16(sP[pb] + lane * 8,     Pbase + pre * 256 + lane * 8);
            cp16(sP[pb] + lane * 8 + 4, Pbase + pre * 256 + lane * 8 + 4);
            cp16(sZ[pb] + lane * 8,     Zbase + pre * 256 + lane * 8);
            cp16(sZ[pb] + lane * 8 + 4, Zbase + pre * 256 + lane * 8 + 4);
        }
        CP_COMMIT();
        CP_WAIT7();
        __syncwarp();

        if (zside) {
            const int base = (chain * NCHUNK + cix) * 256;
            float cl[16];
#pragma unroll
            for (int m = 0; m < 8; m++) unpack2(ypk[m], cl[2 * m], cl[2 * m + 1]);
#pragma unroll
            for (int i = 0; i < 16; i++) g_carry[base + i * 16 + col] = cl[i];

            float yn[16];
#pragma unroll
            for (int i = 0; i < 16; i++) {
                const ulonglong2* pr = (const ulonglong2*)(sP[buf] + i * 16);
                ulonglong2 a0 = pr[0], a1 = pr[1], a2 = pr[2], a3 = pr[3];
                u64 acc0 = ffma2(a0.x, ypk[0], 0ull);
                u64 acc1 = ffma2(a2.x, ypk[4], 0ull);
                acc0 = ffma2(a0.y, ypk[1], acc0);
                acc1 = ffma2(a2.y, ypk[5], acc1);
                acc0 = ffma2(a1.x, ypk[2], acc0);
                acc1 = ffma2(a3.x, ypk[6], acc1);
                acc0 = ffma2(a1.y, ypk[3], acc0);
                acc1 = ffma2(a3.y, ypk[7], acc1);
                float lo, hi;
                unpack2(add2(acc0, acc1), lo, hi);
                yn[i] = lo + hi + sZ[buf][i * 16 + col];
            }
#pragma unroll
            for (int m = 0; m < 8; m++) ypk[m] = pack2(yn[2 * m], yn[2 * m + 1]);
        }
        __syncwarp();
    }
}

// ============================================================================
// Phase 3: final pass, TWO chunks per warp interleaved (doubles per-warp ILP),
// split-k, depth-3 cp.async ring per chunk, direct streaming STG.32.
// ============================================================================
#define P3D 3

__global__ void __launch_bounds__(64) phase3_kernel(
    const float* __restrict__ A, const float* __restrict__ X,
    float* __restrict__ Y)
{
    // [warp][chunk-slot][ring][A:256|X:256]
    __shared__ __align__(16) float sm[2][2][P3D][512];

    const int wid  = threadIdx.x >> 5;
    const int lane = threadIdx.x & 31;
    const int wp   = blockIdx.x * 2 + wid;   // warp-pair id 0..2047
    const int w0   = wp * 2;                 // chunks w0, w0+1 (same chain)
    const int chain = w0 / NCHUNK;
    const int b = chain >> 4;
    const int c = chain & 15;
    const int j = lane & 15;
    const int h = lane >> 4;

    const int t0a = (w0 % NCHUNK) * TT;
    const int base0 = ((b * LL + t0a) * CC + c) * 256;        // chunk 0
    const int base1 = base0 + TT * STEP_STRIDE;               // chunk 1

    const float* srcIn = (h == 0 ? A : X);
    const float* src0 = srcIn + base0 + j * 4;
    const float* src1 = srcIn + base1 + j * 4;
    const int soff = (h == 0 ? 0 : 256) + j * 4;

    // prologue: stage steps 0..P3D-2 for both chunks (one group per step)
#pragma unroll
    for (int d = 0; d < P3D - 1; d++) {
        float* dn0 = sm[wid][0][d] + soff;
        float* dn1 = sm[wid][1][d] + soff;
        const float* s0 = src0 + d * STEP_STRIDE;
        const float* s1 = src1 + d * STEP_STRIDE;
#pragma unroll
        for (int q = 0; q < 4; q++) cp16(dn0 + q * 64, s0 + q * 64);
#pragma unroll
        for (int q = 0; q < 4; q++) cp16(dn1 + q * 64, s1 + q * 64);
        CP_COMMIT();
    }

    // init both states from carries: rows [8h, 8h+8) of column j
    u64 zstA[4], zstB[4];
    {
        const float* cb0 = g_carry + (size_t)w0 * 256;
        const float* cb1 = g_carry + (size_t)(w0 + 1) * 256;
#pragma unroll
        for (int mm = 0; mm < 4; mm++) {
            const int row = 8 * h + 2 * mm;
            zstA[mm] = pack2(cb0[row * 16 + j], cb0[(row + 1) * 16 + j]);
            zstB[mm] = pack2(cb1[row * 16 + j], cb1[(row + 1) * 16 + j]);
        }
    }

    float* out0 = Y + base0 + (8 * h) * 16 + j;
    float* out1 = Y + base1 + (8 * h) * 16 + j;

#pragma unroll 1
    for (int t = 0; t < TT; t++) {
        if (t + P3D - 1 < TT) {
            const int tp = t + P3D - 1;
            float* dn0 = sm[wid][0][tp % P3D] + soff;
            float* dn1 = sm[wid][1][tp % P3D] + soff;
            const float* s0 = src0 + tp * STEP_STRIDE;
            const float* s1 = src1 + tp * STEP_STRIDE;
#pragma unroll
            for (int q = 0; q < 4; q++) cp16(dn0 + q * 64, s0 + q * 64);
#pragma unroll
            for (int q = 0; q < 4; q++) cp16(dn1 + q * 64, s1 + q * 64);
        }
        CP_COMMIT();
        CP_WAIT2();
        __syncwarp();

        const float* AsA = sm[wid][0][t % P3D];
        const float* AsB = sm[wid][1][t % P3D];

        // two independent recurrence steps — chains interleave in issue
        step_z(AsA, h, j, zstA);
        step_z(AsB, h, j, zstB);

        // direct streaming stores for both chunks
        float* o0 = out0 + t * STEP_STRIDE;
        float* o1 = out1 + t * STEP_STRIDE;
#pragma unroll
        for (int mm = 0; mm < 4; mm++) {
            float lo, hi;
            unpack2(zstA[mm], lo, hi);
            __stcs(o0 + (2 * mm) * 16, lo);
            __stcs(o0 + (2 * mm + 1) * 16, hi);
            unpack2(zstB[mm], lo, hi);
            __stcs(o1 + (2 * mm) * 16, lo);
            __stcs(o1 + (2 * mm + 1) * 16, hi);
        }
    }
}

// ============================================================================
extern "C" void kernel_launch(void* const* d_in, const int* in_sizes, int n_in,
                              void* d_out, int out_size)
{
    const float* A = (const float*)d_in[0];
    const float* X = (const float*)d_in[1];
    float* Y = (float*)d_out;

    phase1_kernel<<<TOTCHUNK / 2, 64>>>(A, X);
    phase2_kernel<<<CHAINS, 32>>>();
    phase3_kernel<<<TOTCHUNK / 4, 64>>>(A, X, Y);
}

// round 13
// speedup vs baseline: 1.0770x; 1.0770x over previous
#include <cuda_runtime.h>
#include <cstdint>

// PScan: Y_t = A_t @ Y_{t-1} + X_t  (Y_0 = X_0), per (b,c) chain.
// Shapes: A,X,Y = [B=4, L=2048, C=16, 16, 16] fp32, row-major.
// TT=32 chunked scan; A via cp.async smem ring; X via register LDG prefetch;
// split-k half-warps with f32x2 FFMA; phase3 runs in REVERSE chunk order to
// harvest phase1's L2 tail.

#define BB 4
#define LL 2048
#define CC 16
#define TT 32
#define NCHUNK (LL / TT)            // 64
#define CHAINS (BB * CC)            // 64
#define TOTCHUNK (CHAINS * NCHUNK)  // 4096
#define STEP_STRIDE (CC * 256)

typedef unsigned long long u64;

__device__ float g_Pagg[TOTCHUNK * 256];
__device__ float g_Zagg[TOTCHUNK * 256];
__device__ float g_carry[TOTCHUNK * 256];

__device__ __forceinline__ u64 ffma2(u64 a, u64 b, u64 c) {
    u64 d;
    asm("fma.rn.f32x2 %0, %1, %2, %3;" : "=l"(d) : "l"(a), "l"(b), "l"(c));
    return d;
}
__device__ __forceinline__ u64 add2(u64 a, u64 b) {
    u64 d;
    asm("add.rn.f32x2 %0, %1, %2;" : "=l"(d) : "l"(a), "l"(b));
    return d;
}
__device__ __forceinline__ u64 pack2(float lo, float hi) {
    u64 d;
    asm("mov.b64 %0, {%1, %2};" : "=l"(d) : "f"(lo), "f"(hi));
    return d;
}
__device__ __forceinline__ void unpack2(u64 v, float& lo, float& hi) {
    asm("mov.b64 {%0, %1}, %2;" : "=f"(lo), "=f"(hi) : "l"(v));
}

__device__ __forceinline__ void cp16(float* smem_dst, const float* gsrc) {
    uint32_t s = (uint32_t)__cvta_generic_to_shared(smem_dst);
    asm volatile("cp.async.ca.shared.global [%0], [%1], 16;\n" :: "r"(s), "l"(gsrc));
}
#define CP_COMMIT() asm volatile("cp.async.commit_group;\n" ::: "memory")
#define CP_WAIT0()  asm volatile("cp.async.wait_group 0;\n" ::: "memory")
#define CP_WAIT1()  asm volatile("cp.async.wait_group 1;\n" ::: "memory")
#define CP_WAIT3()  asm volatile("cp.async.wait_group 3;\n" ::: "memory")
#define CP_WAIT7()  asm volatile("cp.async.wait_group 7;\n" ::: "memory")

// partial dot of one A-row k-half (a0,a1 = 4 f32x2) with packed state st[4]
__device__ __forceinline__ float dot8(ulonglong2 a0, ulonglong2 a1, const u64* st)
{
    u64 acc0 = ffma2(a0.x, st[0], 0ull);
    u64 acc1 = ffma2(a0.y, st[1], 0ull);
    acc0 = ffma2(a1.x, st[2], acc0);
    acc1 = ffma2(a1.y, st[3], acc1);
    float lo, hi;
    unpack2(add2(acc0, acc1), lo, hi);
    return lo + hi;
}

// one split-k step advancing Z and P states; xc = this lane's 8 X values
__device__ __forceinline__ void step_zp(const float* As, const float* xc,
                                        int h, int j, u64* zst, u64* pst)
{
    const float* Ah = As + h * 8;
    float zpL[8], zpH[8], ppL[8], ppH[8];
#pragma unroll
    for (int r = 0; r < 8; r++) {
        ulonglong2 a0 = *(const ulonglong2*)(Ah + r * 16);
        ulonglong2 a1 = *(const ulonglong2*)(Ah + r * 16 + 4);
        zpL[r] = dot8(a0, a1, zst);
        ppL[r] = dot8(a0, a1, pst);
        ulonglong2 b0 = *(const ulonglong2*)(Ah + (8 + r) * 16);
        ulonglong2 b1 = *(const ulonglong2*)(Ah + (8 + r) * 16 + 4);
        zpH[r] = dot8(b0, b1, zst);
        ppH[r] = dot8(b0, b1, pst);
    }
    float zn[8], pn[8];
#pragma unroll
    for (int r = 0; r < 8; r++) {
        float zs = h ? zpL[r] : zpH[r];
        float zr = __shfl_xor_sync(0xffffffffu, zs, 16);
        zn[r] = (h ? zpH[r] : zpL[r]) + zr + xc[r];
        float ps = h ? ppL[r] : ppH[r];
        float pr = __shfl_xor_sync(0xffffffffu, ps, 16);
        pn[r] = (h ? ppH[r] : ppL[r]) + pr;
    }
#pragma unroll
    for (int mm = 0; mm < 4; mm++) {
        zst[mm] = pack2(zn[2 * mm], zn[2 * mm + 1]);
        pst[mm] = pack2(pn[2 * mm], pn[2 * mm + 1]);
    }
}

// one split-k step advancing Z only; writes new column values into zn[8]
__device__ __forceinline__ void step_z(const float* As, const float* xc,
                                       int h, int j, u64* zst, float* zn)
{
    const float* Ah = As + h * 8;
    float zpL[8], zpH[8];
#pragma unroll
    for (int r = 0; r < 8; r++) {
        ulonglong2 a0 = *(const ulonglong2*)(Ah + r * 16);
        ulonglong2 a1 = *(const ulonglong2*)(Ah + r * 16 + 4);
        zpL[r] = dot8(a0, a1, zst);
        ulonglong2 b0 = *(const ulonglong2*)(Ah + (8 + r) * 16);
        ulonglong2 b1 = *(const ulonglong2*)(Ah + (8 + r) * 16 + 4);
        zpH[r] = dot8(b0, b1, zst);
    }
#pragma unroll
    for (int r = 0; r < 8; r++) {
        float zs = h ? zpL[r] : zpH[r];
        float zr = __shfl_xor_sync(0xffffffffu, zs, 16);
        zn[r] = (h ? zpH[r] : zpL[r]) + zr + xc[r];
    }
#pragma unroll
    for (int mm = 0; mm < 4; mm++)
        zst[mm] = pack2(zn[2 * mm], zn[2 * mm + 1]);
}

// ============================================================================
// Phase 1: chunk aggregates. A via depth-2 cp.async smem buffer (all 32 lanes
// stage 8 floats each); X via register double-buffer LDG prefetch.
// ============================================================================
__global__ void __launch_bounds__(64) phase1_kernel(
    const float* __restrict__ A, const float* __restrict__ X)
{
    __shared__ __align__(16) float smA[2][2][256];  // [warp][buf][A tile]

    const int wid  = threadIdx.x >> 5;
    const int lane = threadIdx.x & 31;
    const int w    = blockIdx.x * 2 + wid;
    const int chain = w / NCHUNK;
    const int chunk = w % NCHUNK;
    const int b = chain >> 4;
    const int c = chain & 15;
    const int t0 = chunk * TT;
    const int j = lane & 15;
    const int h = lane >> 4;

    const int base0 = ((b * LL + t0) * CC + c) * 256;
    const float* srcA = A + base0 + lane * 8;                 // staging slice
    const float* xsrc = X + base0 + (8 * h) * 16 + j;         // this lane's X

    // prologue: stage A0, load X0
    cp16(&smA[wid][0][lane * 8],     srcA);
    cp16(&smA[wid][0][lane * 8 + 4], srcA + 4);
    CP_COMMIT();

    float xa[8], xb[8];
#pragma unroll
    for (int r = 0; r < 8; r++) xa[r] = xsrc[r * 16];

    u64 zst[4], pst[4];
#pragma unroll
    for (int mm = 0; mm < 4; mm++) {
        zst[mm] = 0ull;
        int k0 = 8 * h + 2 * mm;
        pst[mm] = pack2(j == k0 ? 1.f : 0.f, j == k0 + 1 ? 1.f : 0.f);
    }

#pragma unroll 1
    for (int t = 0; t < TT; t += 2) {
        // ---- step t (uses xa; prefetch xb = X[t+1]; stage A[t+1]) ----
        {
            const float* s2 = srcA + (t + 1) * STEP_STRIDE;
            float* dn = &smA[wid][(t + 1) & 1][lane * 8];
            cp16(dn, s2);
            cp16(dn + 4, s2 + 4);
            CP_COMMIT();
            const float* xs = xsrc + (t + 1) * STEP_STRIDE;
#pragma unroll
            for (int r = 0; r < 8; r++) xb[r] = xs[r * 16];
            CP_WAIT1();
            __syncwarp();
            step_zp(smA[wid][t & 1], xa, h, j, zst, pst);
            __syncwarp();
        }
        // ---- step t+1 (uses xb; prefetch xa = X[t+2]; stage A[t+2]) ----
        {
            if (t + 2 < TT) {
                const float* s2 = srcA + (t + 2) * STEP_STRIDE;
                float* dn = &smA[wid][t & 1][lane * 8];
                cp16(dn, s2);
                cp16(dn + 4, s2 + 4);
                CP_COMMIT();
                const float* xs = xsrc + (t + 2) * STEP_STRIDE;
#pragma unroll
                for (int r = 0; r < 8; r++) xa[r] = xs[r * 16];
                CP_WAIT1();
            } else {
                CP_COMMIT();
                CP_WAIT0();
            }
            __syncwarp();
            step_zp(smA[wid][(t + 1) & 1], xb, h, j, zst, pst);
            __syncwarp();
        }
    }

    const int ab = w * 256;
#pragma unroll
    for (int mm = 0; mm < 4; mm++) {
        const int row = 8 * h + 2 * mm;
        float lo, hi;
        unpack2(zst[mm], lo, hi);
        g_Zagg[ab + row * 16 + j] = lo;
        g_Zagg[ab + (row + 1) * 16 + j] = hi;
        unpack2(pst[mm], lo, hi);
        g_Pagg[ab + row * 16 + j] = lo;
        g_Pagg[ab + (row + 1) * 16 + j] = hi;
    }
}

// ============================================================================
// Phase 2: per-chain scan of NCHUNK aggregates, depth-8 cp.async pipeline.
// ============================================================================
#define P2D 8

__global__ void phase2_kernel()
{
    __shared__ __align__(16) float sP[P2D][256];
    __shared__ __align__(16) float sZ[P2D][256];

    const int chain = blockIdx.x;
    const int lane  = threadIdx.x;
    const int col   = lane & 15;
    const bool zside = (lane < 16);

    const float* Pbase = g_Pagg + (size_t)chain * NCHUNK * 256;
    const float* Zbase = g_Zagg + (size_t)chain * NCHUNK * 256;

#pragma unroll 1
    for (int d = 0; d < P2D - 1; d++) {
        cp16(sP[d] + lane * 8,     Pbase + d * 256 + lane * 8);
        cp16(sP[d] + lane * 8 + 4, Pbase + d * 256 + lane * 8 + 4);
        cp16(sZ[d] + lane * 8,     Zbase + d * 256 + lane * 8);
        cp16(sZ[d] + lane * 8 + 4, Zbase + d * 256 + lane * 8 + 4);
        CP_COMMIT();
    }

    u64 ypk[8];
#pragma unroll
    for (int m = 0; m < 8; m++) ypk[m] = 0ull;

#pragma unroll 1
    for (int cix = 0; cix < NCHUNK; cix++) {
        const int buf = cix & (P2D - 1);
        const int pre = cix + P2D - 1;
        if (pre < NCHUNK) {
            const int pb = pre & (P2D - 1);
            cp16(sP[pb] + lane * 8,     Pbase + pre * 256 + lane * 8);
            cp16(sP[pb] + lane * 8 + 4, Pbase + pre * 256 + lane * 8 + 4);
            cp16(sZ[pb] + lane * 8,     Zbase + pre * 256 + lane * 8);
            cp16(sZ[pb] + lane * 8 + 4, Zbase + pre * 256 + lane * 8 + 4);
        }
        CP_COMMIT();
        CP_WAIT7();
        __syncwarp();

        if (zside) {
            const int base = (chain * NCHUNK + cix) * 256;
            float cl[16];
#pragma unroll
            for (int m = 0; m < 8; m++) unpack2(ypk[m], cl[2 * m], cl[2 * m + 1]);
#pragma unroll
            for (int i = 0; i < 16; i++) g_carry[base + i * 16 + col] = cl[i];

            float yn[16];
#pragma unroll
            for (int i = 0; i < 16; i++) {
                const ulonglong2* pr = (const ulonglong2*)(sP[buf] + i * 16);
                ulonglong2 a0 = pr[0], a1 = pr[1], a2 = pr[2], a3 = pr[3];
                u64 acc0 = ffma2(a0.x, ypk[0], 0ull);
                u64 acc1 = ffma2(a2.x, ypk[4], 0ull);
                acc0 = ffma2(a0.y, ypk[1], acc0);
                acc1 = ffma2(a2.y, ypk[5], acc1);
                acc0 = ffma2(a1.x, ypk[2], acc0);
                acc1 = ffma2(a3.x, ypk[6], acc1);
                acc0 = ffma2(a1.y, ypk[3], acc0);
                acc1 = ffma2(a3.y, ypk[7], acc1);
                float lo, hi;
                unpack2(add2(acc0, acc1), lo, hi);
                yn[i] = lo + hi + sZ[buf][i * 16 + col];
            }
#pragma unroll
            for (int m = 0; m < 8; m++) ypk[m] = pack2(yn[2 * m], yn[2 * m + 1]);
        }
        __syncwarp();
    }
}

// ============================================================================
// Phase 3: final pass in REVERSE chunk order (L2 tail reuse). A via depth-4
// cp.async ring; X via __ldcs register prefetch; Y via streaming STG.32.
// ============================================================================
#define P3D 4

__global__ void __launch_bounds__(64) phase3_kernel(
    const float* __restrict__ A, const float* __restrict__ X,
    float* __restrict__ Y)
{
    __shared__ __align__(16) float smA[2][P3D][256];

    const int wid  = threadIdx.x >> 5;
    const int lane = threadIdx.x & 31;
    // reverse order: block 0 handles the highest-address chunks
    const int w    = (gridDim.x - 1 - blockIdx.x) * 2 + wid;
    const int chain = w / NCHUNK;
    const int chunk = w % NCHUNK;
    const int b = chain >> 4;
    const int c = chain & 15;
    const int t0 = chunk * TT;
    const int j = lane & 15;
    const int h = lane >> 4;

    const int base0 = ((b * LL + t0) * CC + c) * 256;
    const float* srcA = A + base0 + lane * 8;
    const float* xsrc = X + base0 + (8 * h) * 16 + j;

    // prologue: stage A0..A2, load X0
#pragma unroll
    for (int d = 0; d < P3D - 1; d++) {
        const float* s2 = srcA + d * STEP_STRIDE;
        cp16(&smA[wid][d][lane * 8],     s2);
        cp16(&smA[wid][d][lane * 8 + 4], s2 + 4);
        CP_COMMIT();
    }

    float xa[8], xb[8];
#pragma unroll
    for (int r = 0; r < 8; r++) xa[r] = __ldcs(xsrc + r * 16);

    // init state from carry: rows [8h, 8h+8) of column j
    u64 zst[4];
    {
        const int cb = w * 256;
#pragma unroll
        for (int mm = 0; mm < 4; mm++) {
            const int row = 8 * h + 2 * mm;
            zst[mm] = pack2(g_carry[cb + row * 16 + j],
                            g_carry[cb + (row + 1) * 16 + j]);
        }
    }

    float* outc = Y + base0 + (8 * h) * 16 + j;
    float zn[8];

#pragma unroll 1
    for (int t = 0; t < TT; t += 2) {
        // ---- step t (uses xa; prefetch xb; stage A[t+3]) ----
        {
            if (t + P3D - 1 < TT) {
                const float* s2 = srcA + (t + P3D - 1) * STEP_STRIDE;
                float* dn = &smA[wid][(t + P3D - 1) % P3D][lane * 8];
                cp16(dn, s2);
                cp16(dn + 4, s2 + 4);
            }
            CP_COMMIT();
            const float* xs = xsrc + (t + 1) * STEP_STRIDE;
#pragma unroll
            for (int r = 0; r < 8; r++) xb[r] = __ldcs(xs + r * 16);
            CP_WAIT3();
            __syncwarp();
            step_z(smA[wid][t % P3D], xa, h, j, zst, zn);
            float* out = outc + t * STEP_STRIDE;
#pragma unroll
            for (int r = 0; r < 8; r++) __stcs(out + r * 16, zn[r]);
        }
        // ---- step t+1 (uses xb; prefetch xa; stage A[t+4]) ----
        {
            if (t + P3D < TT) {
                const float* s2 = srcA + (t + P3D) * STEP_STRIDE;
                float* dn = &smA[wid][(t + P3D) % P3D][lane * 8];
                cp16(dn, s2);
                cp16(dn + 4, s2 + 4);
            }
            CP_COMMIT();
            if (t + 2 < TT) {
                const float* xs = xsrc + (t + 2) * STEP_STRIDE;
#pragma unroll
                for (int r = 0; r < 8; r++) xa[r] = __ldcs(xs + r * 16);
            }
            CP_WAIT3();
            __syncwarp();
            step_z(smA[wid][(t + 1) % P3D], xb, h, j, zst, zn);
            float* out = outc + (t + 1) * STEP_STRIDE;
#pragma unroll
            for (int r = 0; r < 8; r++) __stcs(out + r * 16, zn[r]);
        }
    }
}

// ============================================================================
extern "C" void kernel_launch(void* const* d_in, const int* in_sizes, int n_in,
                              void* d_out, int out_size)
{
    const float* A = (const float*)d_in[0];
    const float* X = (const float*)d_in[1];
    float* Y = (float*)d_out;

    phase1_kernel<<<TOTCHUNK / 2, 64>>>(A, X);
    phase2_kernel<<<CHAINS, 32>>>();
    phase3_kernel<<<TOTCHUNK / 2, 64>>>(A, X, Y);
}

// round 14
// speedup vs baseline: 1.2363x; 1.1479x over previous
#include <cuda_runtime.h>
#include <cstdint>

// PScan: Y_t = A_t @ Y_{t-1} + X_t  (Y_0 = X_0), per (b,c) chain.
// Shapes: A,X,Y = [B=4, L=2048, C=16, 16, 16] fp32, row-major.
// TT=32 chunked scan; A via cp.async smem ring; X via register LDG prefetch;
// split-k half-warps with f32x2 FFMA; phase3 in reverse chunk order (L2 reuse);
// phase2 = two-level scan (depth ~35 instead of 64).

#define BB 4
#define LL 2048
#define CC 16
#define TT 32
#define NCHUNK (LL / TT)            // 64
#define CHAINS (BB * CC)            // 64
#define TOTCHUNK (CHAINS * NCHUNK)  // 4096
#define STEP_STRIDE (CC * 256)
#define SEG 16                      // chunks per phase2 warp segment

typedef unsigned long long u64;

__device__ float g_Pagg[TOTCHUNK * 256];
__device__ float g_Zagg[TOTCHUNK * 256];
__device__ float g_carry[TOTCHUNK * 256];

__device__ __forceinline__ u64 ffma2(u64 a, u64 b, u64 c) {
    u64 d;
    asm("fma.rn.f32x2 %0, %1, %2, %3;" : "=l"(d) : "l"(a), "l"(b), "l"(c));
    return d;
}
__device__ __forceinline__ u64 add2(u64 a, u64 b) {
    u64 d;
    asm("add.rn.f32x2 %0, %1, %2;" : "=l"(d) : "l"(a), "l"(b));
    return d;
}
__device__ __forceinline__ u64 pack2(float lo, float hi) {
    u64 d;
    asm("mov.b64 %0, {%1, %2};" : "=l"(d) : "f"(lo), "f"(hi));
    return d;
}
__device__ __forceinline__ void unpack2(u64 v, float& lo, float& hi) {
    asm("mov.b64 {%0, %1}, %2;" : "=f"(lo), "=f"(hi) : "l"(v));
}

__device__ __forceinline__ void cp16(float* smem_dst, const float* gsrc) {
    uint32_t s = (uint32_t)__cvta_generic_to_shared(smem_dst);
    asm volatile("cp.async.ca.shared.global [%0], [%1], 16;\n" :: "r"(s), "l"(gsrc));
}
#define CP_COMMIT() asm volatile("cp.async.commit_group;\n" ::: "memory")
#define CP_WAIT0()  asm volatile("cp.async.wait_group 0;\n" ::: "memory")
#define CP_WAIT1()  asm volatile("cp.async.wait_group 1;\n" ::: "memory")
#define CP_WAIT3()  asm volatile("cp.async.wait_group 3;\n" ::: "memory")

// partial dot of one A-row k-half (a0,a1 = 4 f32x2) with packed state st[4]
__device__ __forceinline__ float dot8(ulonglong2 a0, ulonglong2 a1, const u64* st)
{
    u64 acc0 = ffma2(a0.x, st[0], 0ull);
    u64 acc1 = ffma2(a0.y, st[1], 0ull);
    acc0 = ffma2(a1.x, st[2], acc0);
    acc1 = ffma2(a1.y, st[3], acc1);
    float lo, hi;
    unpack2(add2(acc0, acc1), lo, hi);
    return lo + hi;
}

// one split-k step advancing Z and P states; xc = this lane's 8 X values
__device__ __forceinline__ void step_zp(const float* As, const float* xc,
                                        int h, int j, u64* zst, u64* pst)
{
    const float* Ah = As + h * 8;
    float zpL[8], zpH[8], ppL[8], ppH[8];
#pragma unroll
    for (int r = 0; r < 8; r++) {
        ulonglong2 a0 = *(const ulonglong2*)(Ah + r * 16);
        ulonglong2 a1 = *(const ulonglong2*)(Ah + r * 16 + 4);
        zpL[r] = dot8(a0, a1, zst);
        ppL[r] = dot8(a0, a1, pst);
        ulonglong2 b0 = *(const ulonglong2*)(Ah + (8 + r) * 16);
        ulonglong2 b1 = *(const ulonglong2*)(Ah + (8 + r) * 16 + 4);
        zpH[r] = dot8(b0, b1, zst);
        ppH[r] = dot8(b0, b1, pst);
    }
    float zn[8], pn[8];
#pragma unroll
    for (int r = 0; r < 8; r++) {
        float zs = h ? zpL[r] : zpH[r];
        float zr = __shfl_xor_sync(0xffffffffu, zs, 16);
        zn[r] = (h ? zpH[r] : zpL[r]) + zr + xc[r];
        float ps = h ? ppL[r] : ppH[r];
        float pr = __shfl_xor_sync(0xffffffffu, ps, 16);
        pn[r] = (h ? ppH[r] : ppL[r]) + pr;
    }
#pragma unroll
    for (int mm = 0; mm < 4; mm++) {
        zst[mm] = pack2(zn[2 * mm], zn[2 * mm + 1]);
        pst[mm] = pack2(pn[2 * mm], pn[2 * mm + 1]);
    }
}

// one split-k step advancing Z only; writes new column values into zn[8]
__device__ __forceinline__ void step_z(const float* As, const float* xc,
                                       int h, int j, u64* zst, float* zn)
{
    const float* Ah = As + h * 8;
    float zpL[8], zpH[8];
#pragma unroll
    for (int r = 0; r < 8; r++) {
        ulonglong2 a0 = *(const ulonglong2*)(Ah + r * 16);
        ulonglong2 a1 = *(const ulonglong2*)(Ah + r * 16 + 4);
        zpL[r] = dot8(a0, a1, zst);
        ulonglong2 b0 = *(const ulonglong2*)(Ah + (8 + r) * 16);
        ulonglong2 b1 = *(const ulonglong2*)(Ah + (8 + r) * 16 + 4);
        zpH[r] = dot8(b0, b1, zst);
    }
#pragma unroll
    for (int r = 0; r < 8; r++) {
        float zs = h ? zpL[r] : zpH[r];
        float zr = __shfl_xor_sync(0xffffffffu, zs, 16);
        zn[r] = (h ? zpH[r] : zpL[r]) + zr + xc[r];
    }
#pragma unroll
    for (int mm = 0; mm < 4; mm++)
        zst[mm] = pack2(zn[2 * mm], zn[2 * mm + 1]);
}

// ============================================================================
// Phase 1 (R13-proven): chunk aggregates. A via depth-2 cp.async smem buffer;
// X via register double-buffer LDG prefetch.
// ============================================================================
__global__ void __launch_bounds__(64) phase1_kernel(
    const float* __restrict__ A, const float* __restrict__ X)
{
    __shared__ __align__(16) float smA[2][2][256];  // [warp][buf][A tile]

    const int wid  = threadIdx.x >> 5;
    const int lane = threadIdx.x & 31;
    const int w    = blockIdx.x * 2 + wid;
    const int chain = w / NCHUNK;
    const int chunk = w % NCHUNK;
    const int b = chain >> 4;
    const int c = chain & 15;
    const int t0 = chunk * TT;
    const int j = lane & 15;
    const int h = lane >> 4;

    const int base0 = ((b * LL + t0) * CC + c) * 256;
    const float* srcA = A + base0 + lane * 8;
    const float* xsrc = X + base0 + (8 * h) * 16 + j;

    cp16(&smA[wid][0][lane * 8],     srcA);
    cp16(&smA[wid][0][lane * 8 + 4], srcA + 4);
    CP_COMMIT();

    float xa[8], xb[8];
#pragma unroll
    for (int r = 0; r < 8; r++) xa[r] = xsrc[r * 16];

    u64 zst[4], pst[4];
#pragma unroll
    for (int mm = 0; mm < 4; mm++) {
        zst[mm] = 0ull;
        int k0 = 8 * h + 2 * mm;
        pst[mm] = pack2(j == k0 ? 1.f : 0.f, j == k0 + 1 ? 1.f : 0.f);
    }

#pragma unroll 1
    for (int t = 0; t < TT; t += 2) {
        {
            const float* s2 = srcA + (t + 1) * STEP_STRIDE;
            float* dn = &smA[wid][(t + 1) & 1][lane * 8];
            cp16(dn, s2);
            cp16(dn + 4, s2 + 4);
            CP_COMMIT();
            const float* xs = xsrc + (t + 1) * STEP_STRIDE;
#pragma unroll
            for (int r = 0; r < 8; r++) xb[r] = xs[r * 16];
            CP_WAIT1();
            __syncwarp();
            step_zp(smA[wid][t & 1], xa, h, j, zst, pst);
            __syncwarp();
        }
        {
            if (t + 2 < TT) {
                const float* s2 = srcA + (t + 2) * STEP_STRIDE;
                float* dn = &smA[wid][t & 1][lane * 8];
                cp16(dn, s2);
                cp16(dn + 4, s2 + 4);
                CP_COMMIT();
                const float* xs = xsrc + (t + 2) * STEP_STRIDE;
#pragma unroll
                for (int r = 0; r < 8; r++) xa[r] = xs[r * 16];
                CP_WAIT1();
            } else {
                CP_COMMIT();
                CP_WAIT0();
            }
            __syncwarp();
            step_zp(smA[wid][(t + 1) & 1], xb, h, j, zst, pst);
            __syncwarp();
        }
    }

    const int ab = w * 256;
#pragma unroll
    for (int mm = 0; mm < 4; mm++) {
        const int row = 8 * h + 2 * mm;
        float lo, hi;
        unpack2(zst[mm], lo, hi);
        g_Zagg[ab + row * 16 + j] = lo;
        g_Zagg[ab + (row + 1) * 16 + j] = hi;
        unpack2(pst[mm], lo, hi);
        g_Pagg[ab + row * 16 + j] = lo;
        g_Pagg[ab + (row + 1) * 16 + j] = hi;
    }
}

// ============================================================================
// Phase 2: TWO-LEVEL scan. 1 block (4 warps) per chain.
//  pass A: warp s aggregates chunks [16s,16s+16) -> segment (P,Z)   (depth 16)
//  pass B: warp 0 combines 4 segment aggregates -> segment carries  (depth 3)
//  pass C: each warp re-walks its 16 chunks emitting per-chunk carries (16)
// Combines are phase1/phase3 steps with A:=P_chunk, X:=Z_chunk.
// ============================================================================
__global__ void __launch_bounds__(128) phase2_kernel()
{
    __shared__ __align__(16) float sRing[4][2][256];  // per-warp Pc staging
    __shared__ __align__(16) float sPseg[4][256];     // segment aggregates
    __shared__ __align__(16) float sZseg[4][256];
    __shared__ __align__(16) float sCar[4][256];      // segment-start carries

    const int chain = blockIdx.x;
    const int wid  = threadIdx.x >> 5;                // segment id s
    const int lane = threadIdx.x & 31;
    const int j = lane & 15;
    const int h = lane >> 4;

    const float* Pb = g_Pagg + (size_t)(chain * NCHUNK + wid * SEG) * 256;
    const float* Zb = g_Zagg + (size_t)(chain * NCHUNK + wid * SEG) * 256;

    // ---- pass A: segment aggregate ----
    cp16(&sRing[wid][0][lane * 8],     Pb + lane * 8);
    cp16(&sRing[wid][0][lane * 8 + 4], Pb + lane * 8 + 4);
    CP_COMMIT();

    u64 zst[4], pst[4];
#pragma unroll
    for (int mm = 0; mm < 4; mm++) {
        zst[mm] = 0ull;
        int k0 = 8 * h + 2 * mm;
        pst[mm] = pack2(j == k0 ? 1.f : 0.f, j == k0 + 1 ? 1.f : 0.f);
    }

#pragma unroll 1
    for (int c = 0; c < SEG; c++) {
        if (c + 1 < SEG) {
            const float* s2 = Pb + (c + 1) * 256 + lane * 8;
            float* dn = &sRing[wid][(c + 1) & 1][lane * 8];
            cp16(dn, s2);
            cp16(dn + 4, s2 + 4);
            CP_COMMIT();
            CP_WAIT1();
        } else {
            CP_COMMIT();
            CP_WAIT0();
        }
        float zc[8];
        const float* zs = Zb + c * 256 + (8 * h) * 16 + j;
#pragma unroll
        for (int r = 0; r < 8; r++) zc[r] = zs[r * 16];
        __syncwarp();
        step_zp(sRing[wid][c & 1], zc, h, j, zst, pst);
        __syncwarp();
    }

    // publish segment aggregate into smem (row-major)
#pragma unroll
    for (int mm = 0; mm < 4; mm++) {
        const int row = 8 * h + 2 * mm;
        float lo, hi;
        unpack2(zst[mm], lo, hi);
        sZseg[wid][row * 16 + j] = lo;
        sZseg[wid][(row + 1) * 16 + j] = hi;
        unpack2(pst[mm], lo, hi);
        sPseg[wid][row * 16 + j] = lo;
        sPseg[wid][(row + 1) * 16 + j] = hi;
    }
    __syncthreads();

    // ---- pass B: segment-start carries (warp 0 only) ----
    if (wid == 0) {
        u64 car[4];
#pragma unroll
        for (int mm = 0; mm < 4; mm++) car[mm] = 0ull;
#pragma unroll 1
        for (int s = 0; s < 4; s++) {
            // publish car (carry BEFORE segment s)
#pragma unroll
            for (int mm = 0; mm < 4; mm++) {
                const int row = 8 * h + 2 * mm;
                float lo, hi;
                unpack2(car[mm], lo, hi);
                sCar[s][row * 16 + j] = lo;
                sCar[s][(row + 1) * 16 + j] = hi;
            }
            if (s < 3) {
                float zc[8];
#pragma unroll
                for (int r = 0; r < 8; r++) zc[r] = sZseg[s][(8 * h + r) * 16 + j];
                float dummy[8];
                step_z(sPseg[s], zc, h, j, car, dummy);
            }
        }
    }
    __syncthreads();

    // ---- pass C: per-chunk carries within segment ----
    cp16(&sRing[wid][0][lane * 8],     Pb + lane * 8);
    cp16(&sRing[wid][0][lane * 8 + 4], Pb + lane * 8 + 4);
    CP_COMMIT();

    u64 car[4];
#pragma unroll
    for (int mm = 0; mm < 4; mm++) {
        const int row = 8 * h + 2 * mm;
        car[mm] = pack2(sCar[wid][row * 16 + j], sCar[wid][(row + 1) * 16 + j]);
    }

    float* carDst = g_carry + (size_t)(chain * NCHUNK + wid * SEG) * 256;

#pragma unroll 1
    for (int c = 0; c < SEG; c++) {
        if (c + 1 < SEG) {
            const float* s2 = Pb + (c + 1) * 256 + lane * 8;
            float* dn = &sRing[wid][(c + 1) & 1][lane * 8];
            cp16(dn, s2);
            cp16(dn + 4, s2 + 4);
            CP_COMMIT();
            CP_WAIT1();
        } else {
            CP_COMMIT();
            CP_WAIT0();
        }
        // publish carry BEFORE chunk c
        float* dst = carDst + c * 256 + (8 * h) * 16 + j;
#pragma unroll
        for (int mm = 0; mm < 4; mm++) {
            float lo, hi;
            unpack2(car[mm], lo, hi);
            dst[(2 * mm) * 16] = lo;
            dst[(2 * mm + 1) * 16] = hi;
        }
        float zc[8];
        const float* zs = Zb + c * 256 + (8 * h) * 16 + j;
#pragma unroll
        for (int r = 0; r < 8; r++) zc[r] = zs[r * 16];
        __syncwarp();
        float dummy[8];
        step_z(sRing[wid][c & 1], zc, h, j, car, dummy);
        __syncwarp();
    }
}

// ============================================================================
// Phase 3 (R13-proven): final pass in REVERSE chunk order. A via depth-4
// cp.async ring; X via __ldcs register prefetch; Y via streaming STG.32.
// ============================================================================
#define P3D 4

__global__ void __launch_bounds__(64) phase3_kernel(
    const float* __restrict__ A, const float* __restrict__ X,
    float* __restrict__ Y)
{
    __shared__ __align__(16) float smA[2][P3D][256];

    const int wid  = threadIdx.x >> 5;
    const int lane = threadIdx.x & 31;
    const int w    = (gridDim.x - 1 - blockIdx.x) * 2 + wid;
    const int chain = w / NCHUNK;
    const int chunk = w % NCHUNK;
    const int b = chain >> 4;
    const int c = chain & 15;
    const int t0 = chunk * TT;
    const int j = lane & 15;
    const int h = lane >> 4;

    const int base0 = ((b * LL + t0) * CC + c) * 256;
    const float* srcA = A + base0 + lane * 8;
    const float* xsrc = X + base0 + (8 * h) * 16 + j;

#pragma unroll
    for (int d = 0; d < P3D - 1; d++) {
        const float* s2 = srcA + d * STEP_STRIDE;
        cp16(&smA[wid][d][lane * 8],     s2);
        cp16(&smA[wid][d][lane * 8 + 4], s2 + 4);
        CP_COMMIT();
    }

    float xa[8], xb[8];
#pragma unroll
    for (int r = 0; r < 8; r++) xa[r] = __ldcs(xsrc + r * 16);

    u64 zst[4];
    {
        const int cb = w * 256;
#pragma unroll
        for (int mm = 0; mm < 4; mm++) {
            const int row = 8 * h + 2 * mm;
            zst[mm] = pack2(g_carry[cb + row * 16 + j],
                            g_carry[cb + (row + 1) * 16 + j]);
        }
    }

    float* outc = Y + base0 + (8 * h) * 16 + j;
    float zn[8];

#pragma unroll 1
    for (int t = 0; t < TT; t += 2) {
        {
            if (t + P3D - 1 < TT) {
                const float* s2 = srcA + (t + P3D - 1) * STEP_STRIDE;
                float* dn = &smA[wid][(t + P3D - 1) % P3D][lane * 8];
                cp16(dn, s2);
                cp16(dn + 4, s2 + 4);
            }
            CP_COMMIT();
            const float* xs = xsrc + (t + 1) * STEP_STRIDE;
#pragma unroll
            for (int r = 0; r < 8; r++) xb[r] = __ldcs(xs + r * 16);
            CP_WAIT3();
            __syncwarp();
            step_z(smA[wid][t % P3D], xa, h, j, zst, zn);
            float* out = outc + t * STEP_STRIDE;
#pragma unroll
            for (int r = 0; r < 8; r++) __stcs(out + r * 16, zn[r]);
        }
        {
            if (t + P3D < TT) {
                const float* s2 = srcA + (t + P3D) * STEP_STRIDE;
                float* dn = &smA[wid][(t + P3D) % P3D][lane * 8];
                cp16(dn, s2);
                cp16(dn + 4, s2 + 4);
            }
            CP_COMMIT();
            if (t + 2 < TT) {
                const float* xs = xsrc + (t + 2) * STEP_STRIDE;
#pragma unroll
                for (int r = 0; r < 8; r++) xa[r] = __ldcs(xs + r * 16);
            }
            CP_WAIT3();
            __syncwarp();
            step_z(smA[wid][(t + 1) % P3D], xb, h, j, zst, zn);
            float* out = outc + (t + 1) * STEP_STRIDE;
#pragma unroll
            for (int r = 0; r < 8; r++) __stcs(out + r * 16, zn[r]);
        }
    }
}

// ============================================================================
extern "C" void kernel_launch(void* const* d_in, const int* in_sizes, int n_in,
                              void* d_out, int out_size)
{
    const float* A = (const float*)d_in[0];
    const float* X = (const float*)d_in[1];
    float* Y = (float*)d_out;

    phase1_kernel<<<TOTCHUNK / 2, 64>>>(A, X);
    phase2_kernel<<<CHAINS, 128>>>();
    phase3_kernel<<<TOTCHUNK / 2, 64>>>(A, X, Y);
}